// round 10
// baseline (speedup 1.0000x reference)
#include <cuda_runtime.h>
#include <cuda_bf16.h>
#include <cstdint>

#define TILE_H 16
#define TILE_W 32
#define HALO_H (TILE_H + 2)        // 18
#define ROWSPAN 40                 // padded row: gmem cols [tw0-4, tw0+36), 160B aligned
#define PLANE  (HALO_H * ROWSPAN)  // 720 floats per channel plane
#define CCH    64
#define HH     128
#define WWD    128
#define HW     (HH * WWD)
#define NTAP   9
#define WSTRIDE 12                 // 9 weights padded to 12 floats, 16B-aligned rows
#define CHUNK  8
#define NCHUNK (CCH / CHUNK)       // 8
#define NSLOT4 (CHUNK * HALO_H * 10)   // 1440 float4 slots per chunk staging

#define XS_ELEMS (CHUNK * PLANE)             // 5760 floats per buffer
#define WS_ELEMS (NTAP * CCH * WSTRIDE)      // 6912 floats = 27648 B
#define SMEM_BYTES (2 * XS_ELEMS * 4)        // 46080 B

// Weights live in constant memory: uniform-const port (LDCU), off the L1/LDS path.
__constant__ float c_ws[WS_ELEMS];
__device__   float g_wscratch[WS_ELEMS];

extern __shared__ float smem[];

typedef unsigned long long u64t;

#define CP_COMMIT() asm volatile("cp.async.commit_group;\n" ::: "memory")
#define CP_WAIT0()  asm volatile("cp.async.wait_group 0;\n" ::: "memory")

__device__ __forceinline__ u64t pack2(float lo, float hi) {
    u64t r;
    asm("mov.b64 %0, {%1, %2};" : "=l"(r) : "r"(__float_as_uint(lo)), "r"(__float_as_uint(hi)));
    return r;
}
__device__ __forceinline__ u64t dup2(float v) {
    u64t r;
    asm("mov.b64 %0, {%1, %1};" : "=l"(r) : "r"(__float_as_uint(v)));
    return r;
}
// d = a*b + c elementwise on packed f32x2 -> single FFMA2 in SASS
__device__ __forceinline__ u64t ffma2(u64t a, u64t b, u64t c) {
    u64t d;
    asm("fma.rn.f32x2 %0, %1, %2, %3;" : "=l"(d) : "l"(a), "l"(b), "l"(c));
    return d;
}

// Pre-pass: reorder W[k][c][tap] -> [tap][c][12] with k contiguous (pair-packed for FFMA2).
__global__ void reorder_weights_kernel(const float* __restrict__ Wt)
{
    for (int i = blockIdx.x * blockDim.x + threadIdx.x;
         i < NTAP * CCH * NTAP; i += gridDim.x * blockDim.x) {
        int k   = i / (CCH * NTAP);
        int rem = i - k * (CCH * NTAP);
        int c   = rem / NTAP;
        int tap = rem - c * NTAP;
        g_wscratch[(tap * CCH + c) * WSTRIDE + k] = Wt[(k * CCH + c) * NTAP + tap];
    }
}

// One 8-channel chunk = 1440 aligned float4 copies; 6 slots/thread, descriptors
// precomputed once. Invalid slots zero-fill via cp.async src-size=0, which also
// writes the conv's zero halo at image borders.
__device__ __forceinline__ void stage_async(float* __restrict__ buf,
                                            const float* __restrict__ xc,
                                            const int* __restrict__ goff,
                                            int tid)
{
    uint32_t sa = (uint32_t)__cvta_generic_to_shared(buf) + (uint32_t)tid * 16u;
    #pragma unroll
    for (int s = 0; s < 5; ++s) {
        const int o = goff[s];
        const float* src = xc + (o >= 0 ? o : 0);
        const int z = (o >= 0) ? 16 : 0;
        asm volatile("cp.async.cg.shared.global [%0], [%1], 16, %2;\n"
                     :: "r"(sa + (uint32_t)s * 4096u), "l"(src), "r"(z) : "memory");
    }
    if (tid < (NSLOT4 - 5 * 256)) {   // tid < 160
        const int o = goff[5];
        const float* src = xc + (o >= 0 ? o : 0);
        const int z = (o >= 0) ? 16 : 0;
        asm volatile("cp.async.cg.shared.global [%0], [%1], 16, %2;\n"
                     :: "r"(sa + 5u * 4096u), "l"(src), "r"(z) : "memory");
    }
}

__global__ __launch_bounds__(256, 2)
void ahpf_fused_kernel(const float* __restrict__ x,
                       const float* __restrict__ bias,
                       float* __restrict__ out)
{
    float* xsA = smem;                         // buffer 0: [8][18][40]
    float* xsB = smem + XS_ELEMS;              // buffer 1
    float* xbuf[2] = { xsA, xsB };

    const int tw0 = blockIdx.x * TILE_W;
    const int th0 = blockIdx.y * TILE_H;
    const int b   = blockIdx.z;
    const int tid = threadIdx.x;

    // --- Precompute float4 staging descriptors (6 slots/thread, reused 15x) ---
    int goff[6];
    #pragma unroll
    for (int s = 0; s < 6; ++s) {
        const int i = tid + 256 * s;
        int o = -1;
        if (i < NSLOT4) {
            const int chan = i / 180;          // 180 float4 per channel plane
            const int p    = i - chan * 180;
            const int r    = p / 10;           // halo row 0..17
            const int g    = p - r * 10;       // 4-col group 0..9
            const int row  = th0 - 1 + r;
            const int col  = tw0 - 4 + 4 * g;  // group fully in or out (4 | tw0)
            if (row >= 0 && row < HH && col >= 0 && col < WWD)
                o = chan * HW + row * WWD + col;
        }
        goff[s] = o;
    }

    const float* xb = x + (size_t)b * CCH * HW;

    // --- Prologue: start chunk 0 copy ---
    stage_async(xbuf[0], xb, goff, tid);
    CP_COMMIT();

    const int w   = tid & 31;
    const int h2  = tid >> 5;            // pixel rows 2*h2, 2*h2+1
    const int gh0 = th0 + 2 * h2;
    const int gw  = tw0 + w;

    // Packed accumulators: accA = pixel0 k-pairs (0,1)(2,3)(4,5)(6,7), acc8a = k=8
    u64t accA[4], accB[4];
    float acc8a, acc8b;
    #pragma unroll
    for (int j = 0; j < 4; ++j) {
        u64t bp = pack2(bias[2 * j], bias[2 * j + 1]);
        accA[j] = bp; accB[j] = bp;
    }
    acc8a = bias[8]; acc8b = acc8a;

    CP_WAIT0();
    __syncthreads();

    // ---------------- Conv via FFMA2, weights from constant port -----------------
    for (int ch = 0; ch < NCHUNK; ++ch) {
        if (ch + 1 < NCHUNK) {
            stage_async(xbuf[(ch + 1) & 1], xb + (size_t)(ch + 1) * CHUNK * HW, goff, tid);
            CP_COMMIT();
        }

        const float* xsc = xbuf[ch & 1];
        #pragma unroll 2
        for (int c = 0; c < CHUNK; ++c) {
            // union of the two pixels' 3x3 neighborhoods: 4 rows x 3 cols
            const float* xr = xsc + c * PLANE + (2 * h2) * ROWSPAN + (w + 3);
            float xv[4][3];
            #pragma unroll
            for (int r = 0; r < 4; ++r)
                #pragma unroll
                for (int j = 0; j < 3; ++j)
                    xv[r][j] = xr[r * ROWSPAN + j];

            const int cg = ch * CHUNK + c;
            #pragma unroll
            for (int di = 0; di < 3; ++di) {
                #pragma unroll
                for (int dj = 0; dj < 3; ++dj) {
                    // uniform constant loads: (k,k+1) pairs straight into b64 operands
                    const float* wq = c_ws + ((di * 3 + dj) * CCH + cg) * WSTRIDE;
                    const ulonglong2 wp0 = *reinterpret_cast<const ulonglong2*>(wq);
                    const ulonglong2 wp1 = *reinterpret_cast<const ulonglong2*>(wq + 4);
                    const float      w8  = wq[8];
                    const float a0 = xv[di][dj];
                    const float a1 = xv[di + 1][dj];
                    const u64t a0d = dup2(a0);
                    const u64t a1d = dup2(a1);
                    accA[0] = ffma2(a0d, wp0.x, accA[0]);
                    accA[1] = ffma2(a0d, wp0.y, accA[1]);
                    accA[2] = ffma2(a0d, wp1.x, accA[2]);
                    accA[3] = ffma2(a0d, wp1.y, accA[3]);
                    acc8a   = fmaf(a0, w8, acc8a);
                    accB[0] = ffma2(a1d, wp0.x, accB[0]);
                    accB[1] = ffma2(a1d, wp0.y, accB[1]);
                    accB[2] = ffma2(a1d, wp1.x, accB[2]);
                    accB[3] = ffma2(a1d, wp1.y, accB[3]);
                    acc8b   = fmaf(a1, w8, acc8b);
                }
            }
        }

        if (ch + 1 < NCHUNK) CP_WAIT0();
        __syncthreads();
    }

    // Unpack accumulators
    float acc0[NTAP], acc1[NTAP];
    #pragma unroll
    for (int j = 0; j < 4; ++j) {
        float2 fa = *reinterpret_cast<float2*>(&accA[j]);
        float2 fb = *reinterpret_cast<float2*>(&accB[j]);
        acc0[2 * j] = fa.x; acc0[2 * j + 1] = fa.y;
        acc1[2 * j] = fb.x; acc1[2 * j + 1] = fb.y;
    }
    acc0[8] = acc8a; acc1[8] = acc8b;

    // ---------------- softmax * hamming, renormalized (denominator cancels) -----
    const float hamv[NTAP] = {0.0064f, 0.08f, 0.0064f,
                              0.08f,   1.0f,  0.08f,
                              0.0064f, 0.08f, 0.0064f};
    float mask0[NTAP], mask1[NTAP];
    {
        float mx0 = acc0[0], mx1 = acc1[0];
        #pragma unroll
        for (int k = 1; k < NTAP; ++k) { mx0 = fmaxf(mx0, acc0[k]); mx1 = fmaxf(mx1, acc1[k]); }
        float s0 = 0.f, s1 = 0.f;
        #pragma unroll
        for (int k = 0; k < NTAP; ++k) {
            float e0 = __expf(acc0[k] - mx0) * hamv[k];
            float e1 = __expf(acc1[k] - mx1) * hamv[k];
            mask0[k] = e0; mask1[k] = e1;
            s0 += e0; s1 += e1;
        }
        const float i0 = __fdividef(1.f, s0);
        const float i1 = __fdividef(1.f, s1);
        #pragma unroll
        for (int k = 0; k < NTAP; ++k) { mask0[k] *= i0; mask1[k] *= i1; }
    }

    // ---------------- reflect-padded offsets (shared by the pixel pair) ---------
    int roff[4], coff[3];
    #pragma unroll
    for (int i = 0; i < 4; ++i) {
        int g = gh0 - 1 + i;
        g = (g < 0) ? 1 : ((g >= HH) ? (HH - 2) : g);
        roff[i] = (g - th0 + 1) * ROWSPAN;
    }
    #pragma unroll
    for (int j = 0; j < 3; ++j) {
        int g = gw - 1 + j;
        g = (g < 0) ? 1 : ((g >= WWD) ? (WWD - 2) : g);
        coff[j] = g - tw0 + 4;
    }

    // ---------------- CARAFE lowpass + highpass residual ------------------------
    // Reverse walk: chunk NCHUNK-1 is still resident in buf[(NCHUNK-1)&1].
    float* outb = out + ((size_t)b * CCH) * HW + (size_t)gh0 * WWD + gw;

    for (int chr = 0; chr < NCHUNK; ++chr) {
        const int ch = NCHUNK - 1 - chr;
        if (ch > 0) {
            stage_async(xbuf[(ch - 1) & 1], xb + (size_t)(ch - 1) * CHUNK * HW, goff, tid);
            CP_COMMIT();
        }

        const float* xsc = xbuf[ch & 1];
        #pragma unroll 2
        for (int c = 0; c < CHUNK; ++c) {
            const float* xc = xsc + c * PLANE;
            float v[4][3];
            #pragma unroll
            for (int i = 0; i < 4; ++i)
                #pragma unroll
                for (int j = 0; j < 3; ++j)
                    v[i][j] = xc[roff[i] + coff[j]];

            // v[1][1] = center of pixel0, v[2][1] = center of pixel1 (never reflected)
            float lp0 = mask0[0] * v[0][0];
            float lp1 = mask1[0] * v[1][0];
            #pragma unroll
            for (int di = 0; di < 3; ++di)
                #pragma unroll
                for (int dj = 0; dj < 3; ++dj) {
                    if (di == 0 && dj == 0) continue;
                    lp0 = fmaf(mask0[di * 3 + dj], v[di][dj],     lp0);
                    lp1 = fmaf(mask1[di * 3 + dj], v[di + 1][dj], lp1);
                }

            const size_t co = (size_t)(ch * CHUNK + c) * HW;
            outb[co]       = 2.f * v[1][1] - lp0;
            outb[co + WWD] = 2.f * v[2][1] - lp1;
        }

        if (ch > 0) {
            CP_WAIT0();
            __syncthreads();
        }
    }
}

extern "C" void kernel_launch(void* const* d_in, const int* in_sizes, int n_in,
                              void* d_out, int out_size)
{
    const float* x  = (const float*)d_in[0];
    const float* Wt = (const float*)d_in[1];
    const float* bs = (const float*)d_in[2];
    float* out = (float*)d_out;

    const int B = in_sizes[0] / (CCH * HW);

    // 1) reorder weights into device scratch
    reorder_weights_kernel<<<8, 256>>>(Wt);

    // 2) scratch -> constant bank (capturable memcpy node, device-to-device)
    void* src = nullptr;
    cudaGetSymbolAddress(&src, g_wscratch);
    cudaMemcpyToSymbolAsync(c_ws, src, WS_ELEMS * sizeof(float), 0,
                            cudaMemcpyDeviceToDevice, 0);

    // 3) fused main kernel
    cudaFuncSetAttribute(ahpf_fused_kernel,
                         cudaFuncAttributeMaxDynamicSharedMemorySize, SMEM_BYTES);
    dim3 grid(WWD / TILE_W, HH / TILE_H, B);
    ahpf_fused_kernel<<<grid, 256, SMEM_BYTES>>>(x, bs, out);
}

// round 11
// speedup vs baseline: 2.2310x; 2.2310x over previous
#include <cuda_runtime.h>
#include <cuda_bf16.h>
#include <cstdint>

#define TILE_H 16
#define TILE_W 32
#define HALO_H (TILE_H + 2)        // 18
#define ROWSPAN 40                 // padded row: gmem cols [tw0-4, tw0+36), 160B aligned
#define PLANE  (HALO_H * ROWSPAN)  // 720 floats per channel plane
#define CCH    64
#define HH     128
#define WWD    128
#define HW     (HH * WWD)
#define NTAP   9
#define CHUNK  8
#define NCHUNK (CCH / CHUNK)       // 8
#define NBUF   3
#define NSLOT4 (CHUNK * HALO_H * 10)   // 1440 float4 slots per chunk staging

#define XS_ELEMS  (CHUNK * PLANE)      // 5760 floats per buffer
#define WSA_ELEMS (NTAP * CCH * 8)     // 4608: k=0..7 pairs, [tap][c][8]
#define WSB_ELEMS (CCH * 12)           // 768:  k=8 weights, [c][tap] padded to 12
#define SMEM_BYTES ((NBUF * XS_ELEMS + WSA_ELEMS + WSB_ELEMS) * 4)  // 90624 B -> 2 CTA/SM

extern __shared__ float smem[];

typedef unsigned long long u64t;

#define CP_COMMIT() asm volatile("cp.async.commit_group;\n" ::: "memory")
#define CP_WAIT0()  asm volatile("cp.async.wait_group 0;\n" ::: "memory")
#define CP_WAIT1()  asm volatile("cp.async.wait_group 1;\n" ::: "memory")

__device__ __forceinline__ u64t pack2(float lo, float hi) {
    u64t r;
    asm("mov.b64 %0, {%1, %2};" : "=l"(r) : "r"(__float_as_uint(lo)), "r"(__float_as_uint(hi)));
    return r;
}
__device__ __forceinline__ u64t dup2(float v) {
    u64t r;
    asm("mov.b64 %0, {%1, %1};" : "=l"(r) : "r"(__float_as_uint(v)));
    return r;
}
// d = a*b + c elementwise on packed f32x2 -> single FFMA2 in SASS
__device__ __forceinline__ u64t ffma2(u64t a, u64t b, u64t c) {
    u64t d;
    asm("fma.rn.f32x2 %0, %1, %2, %3;" : "=l"(d) : "l"(a), "l"(b), "l"(c));
    return d;
}

// One 8-channel chunk = 1440 aligned float4 copies; 6 slots/thread, descriptors
// precomputed once. Invalid slots zero-fill via cp.async src-size=0, which also
// writes the conv's zero halo at image borders.
__device__ __forceinline__ void stage_async(float* __restrict__ buf,
                                            const float* __restrict__ xc,
                                            const int* __restrict__ goff,
                                            int tid)
{
    uint32_t sa = (uint32_t)__cvta_generic_to_shared(buf) + (uint32_t)tid * 16u;
    #pragma unroll
    for (int s = 0; s < 5; ++s) {
        const int o = goff[s];
        const float* src = xc + (o >= 0 ? o : 0);
        const int z = (o >= 0) ? 16 : 0;
        asm volatile("cp.async.cg.shared.global [%0], [%1], 16, %2;\n"
                     :: "r"(sa + (uint32_t)s * 4096u), "l"(src), "r"(z) : "memory");
    }
    if (tid < (NSLOT4 - 5 * 256)) {   // tid < 160
        const int o = goff[5];
        const float* src = xc + (o >= 0 ? o : 0);
        const int z = (o >= 0) ? 16 : 0;
        asm volatile("cp.async.cg.shared.global [%0], [%1], 16, %2;\n"
                     :: "r"(sa + 5u * 4096u), "l"(src), "r"(z) : "memory");
    }
}

__global__ __launch_bounds__(256, 2)
void ahpf_fused_kernel(const float* __restrict__ x,
                       const float* __restrict__ Wt,
                       const float* __restrict__ bias,
                       float* __restrict__ out)
{
    float* xb0 = smem;
    float* xb1 = smem + XS_ELEMS;
    float* xb2 = smem + 2 * XS_ELEMS;
    float* wsA = smem + NBUF * XS_ELEMS;            // [tap][c][8] : k=0..7
    float* wsB = wsA + WSA_ELEMS;                   // [c][12]     : k=8 per tap
    float* xbuf[NBUF] = { xb0, xb1, xb2 };

    const int tw0 = blockIdx.x * TILE_W;
    const int th0 = blockIdx.y * TILE_H;
    const int b   = blockIdx.z;
    const int tid = threadIdx.x;

    // --- Precompute float4 staging descriptors (6 slots/thread, reused 15x) ---
    int goff[6];
    #pragma unroll
    for (int s = 0; s < 6; ++s) {
        const int i = tid + 256 * s;
        int o = -1;
        if (i < NSLOT4) {
            const int chan = i / 180;          // 180 float4 per channel plane
            const int p    = i - chan * 180;
            const int r    = p / 10;           // halo row 0..17
            const int g    = p - r * 10;       // 4-col group 0..9
            const int row  = th0 - 1 + r;
            const int col  = tw0 - 4 + 4 * g;  // group fully in or out (4 | tw0)
            if (row >= 0 && row < HH && col >= 0 && col < WWD)
                o = chan * HW + row * WWD + col;
        }
        goff[s] = o;
    }

    const float* xb = x + (size_t)b * CCH * HW;

    // --- Prologue: start chunk 0 and 1 copies, stage weights meanwhile ---
    stage_async(xbuf[0], xb, goff, tid);
    CP_COMMIT();
    stage_async(xbuf[1], xb + (size_t)CHUNK * HW, goff, tid);
    CP_COMMIT();

    // Weight split: wsA[(tap*64 + c)*8 + k] = W[k][c][tap] for k<8;
    //               wsB[c*12 + tap]        = W[8][c][tap]
    for (int i = tid; i < NTAP * CCH * NTAP; i += 256) {
        int k   = i / (CCH * NTAP);
        int rem = i - k * (CCH * NTAP);
        int c   = rem / NTAP;
        int tap = rem - c * NTAP;
        float v = Wt[(k * CCH + c) * NTAP + tap];
        if (k < 8) wsA[(tap * CCH + c) * 8 + k] = v;
        else       wsB[c * 12 + tap] = v;
    }

    const int w   = tid & 31;
    const int h2  = tid >> 5;            // pixel rows 2*h2, 2*h2+1
    const int gh0 = th0 + 2 * h2;
    const int gw  = tw0 + w;

    // Packed accumulators: accA = pixel0 k-pairs (0,1)(2,3)(4,5)(6,7), acc8a = k=8
    u64t accA[4], accB[4];
    float acc8a, acc8b;
    #pragma unroll
    for (int j = 0; j < 4; ++j) {
        u64t bp = pack2(bias[2 * j], bias[2 * j + 1]);
        accA[j] = bp; accB[j] = bp;
    }
    acc8a = bias[8]; acc8b = acc8a;

    CP_WAIT1();           // chunk 0 resident; chunk 1 may still fly
    __syncthreads();      // + weights visible

    // ---------------- Conv via FFMA2: 9 logits for each of 2 stacked pixels ------
    for (int ch = 0; ch < NCHUNK; ++ch) {
        if (ch > 0) {
            if (ch < NCHUNK - 1) CP_WAIT1(); else CP_WAIT0();
            __syncthreads();
        }
        if (ch + 2 < NCHUNK) {   // stage 2 ahead into the buffer freed last iter
            stage_async(xbuf[(ch + 2) % NBUF], xb + (size_t)(ch + 2) * CHUNK * HW, goff, tid);
            CP_COMMIT();
        }

        const float* xsc = xbuf[ch % NBUF];
        #pragma unroll 2
        for (int c = 0; c < CHUNK; ++c) {
            const int cg = ch * CHUNK + c;

            // k=8 weights for all 9 taps: 3 LDS once per channel
            const float* w8p = wsB + cg * 12;
            const float4 w8lo = *reinterpret_cast<const float4*>(w8p);
            const float4 w8mi = *reinterpret_cast<const float4*>(w8p + 4);
            const float  w8hi = w8p[8];
            const float w8v[NTAP] = { w8lo.x, w8lo.y, w8lo.z, w8lo.w,
                                      w8mi.x, w8mi.y, w8mi.z, w8mi.w, w8hi };

            // union of the two pixels' 3x3 neighborhoods: 4 rows x 3 cols
            const float* xr = xsc + c * PLANE + (2 * h2) * ROWSPAN + (w + 3);
            float xv[4][3];
            #pragma unroll
            for (int r = 0; r < 4; ++r)
                #pragma unroll
                for (int j = 0; j < 3; ++j)
                    xv[r][j] = xr[r * ROWSPAN + j];

            #pragma unroll
            for (int di = 0; di < 3; ++di) {
                #pragma unroll
                for (int dj = 0; dj < 3; ++dj) {
                    const int tap = di * 3 + dj;
                    // k=0..7 pairs: 32B row -> two LDS.128
                    const float* wq = wsA + (tap * CCH + cg) * 8;
                    const ulonglong2 wp = *reinterpret_cast<const ulonglong2*>(wq);
                    const ulonglong2 wr = *reinterpret_cast<const ulonglong2*>(wq + 4);
                    const float a0 = xv[di][dj];
                    const float a1 = xv[di + 1][dj];
                    const u64t a0d = dup2(a0);
                    const u64t a1d = dup2(a1);
                    accA[0] = ffma2(a0d, wp.x, accA[0]);
                    accA[1] = ffma2(a0d, wp.y, accA[1]);
                    accA[2] = ffma2(a0d, wr.x, accA[2]);
                    accA[3] = ffma2(a0d, wr.y, accA[3]);
                    acc8a   = fmaf(a0, w8v[tap], acc8a);
                    accB[0] = ffma2(a1d, wp.x, accB[0]);
                    accB[1] = ffma2(a1d, wp.y, accB[1]);
                    accB[2] = ffma2(a1d, wr.x, accB[2]);
                    accB[3] = ffma2(a1d, wr.y, accB[3]);
                    acc8b   = fmaf(a1, w8v[tap], acc8b);
                }
            }
        }
    }

    // Unpack accumulators
    float acc0[NTAP], acc1[NTAP];
    #pragma unroll
    for (int j = 0; j < 4; ++j) {
        float2 fa = *reinterpret_cast<float2*>(&accA[j]);
        float2 fb = *reinterpret_cast<float2*>(&accB[j]);
        acc0[2 * j] = fa.x; acc0[2 * j + 1] = fa.y;
        acc1[2 * j] = fb.x; acc1[2 * j + 1] = fb.y;
    }
    acc0[8] = acc8a; acc1[8] = acc8b;

    // ---------------- softmax * hamming, renormalized (denominator cancels) -----
    const float hamv[NTAP] = {0.0064f, 0.08f, 0.0064f,
                              0.08f,   1.0f,  0.08f,
                              0.0064f, 0.08f, 0.0064f};
    float mask0[NTAP], mask1[NTAP];
    {
        float mx0 = acc0[0], mx1 = acc1[0];
        #pragma unroll
        for (int k = 1; k < NTAP; ++k) { mx0 = fmaxf(mx0, acc0[k]); mx1 = fmaxf(mx1, acc1[k]); }
        float s0 = 0.f, s1 = 0.f;
        #pragma unroll
        for (int k = 0; k < NTAP; ++k) {
            float e0 = __expf(acc0[k] - mx0) * hamv[k];
            float e1 = __expf(acc1[k] - mx1) * hamv[k];
            mask0[k] = e0; mask1[k] = e1;
            s0 += e0; s1 += e1;
        }
        const float i0 = __fdividef(1.f, s0);
        const float i1 = __fdividef(1.f, s1);
        #pragma unroll
        for (int k = 0; k < NTAP; ++k) { mask0[k] *= i0; mask1[k] *= i1; }
    }

    // ---------------- reflect-padded offsets (shared by the pixel pair) ---------
    int roff[4], coff[3];
    #pragma unroll
    for (int i = 0; i < 4; ++i) {
        int g = gh0 - 1 + i;
        g = (g < 0) ? 1 : ((g >= HH) ? (HH - 2) : g);
        roff[i] = (g - th0 + 1) * ROWSPAN;
    }
    #pragma unroll
    for (int j = 0; j < 3; ++j) {
        int g = gw - 1 + j;
        g = (g < 0) ? 1 : ((g >= WWD) ? (WWD - 2) : g);
        coff[j] = g - tw0 + 4;
    }

    // ---------------- CARAFE lowpass + highpass residual ------------------------
    // At conv end the 3 buffers hold chunks 6(buf0), 7(buf1), 5(buf2) — all
    // resident. Reverse walk 7..0; chunk ch lives in buf[ch % 3] throughout.
    // Staging: chunk 5-chr is staged at iter chr (chr=1..5) into the buffer
    // freed by the previous iter's compute; consumed two iters later.
    float* outb = out + ((size_t)b * CCH) * HW + (size_t)gh0 * WWD + gw;

    for (int chr = 0; chr < NCHUNK; ++chr) {
        const int ch = NCHUNK - 1 - chr;

        if (chr >= 3) {                 // consuming a staged chunk
            if (chr < NCHUNK - 1) CP_WAIT1(); else CP_WAIT0();
            __syncthreads();
        } else if (chr >= 1) {
            __syncthreads();            // buffer-reuse hazard for the stage below
        }

        if (chr >= 1 && chr <= 5) {     // stage chunk 5-chr into just-freed buffer
            const int cs = 5 - chr;
            stage_async(xbuf[cs % NBUF], xb + (size_t)cs * CHUNK * HW, goff, tid);
            CP_COMMIT();
        }

        const float* xsc = xbuf[ch % NBUF];
        #pragma unroll 2
        for (int c = 0; c < CHUNK; ++c) {
            const float* xc = xsc + c * PLANE;
            float v[4][3];
            #pragma unroll
            for (int i = 0; i < 4; ++i)
                #pragma unroll
                for (int j = 0; j < 3; ++j)
                    v[i][j] = xc[roff[i] + coff[j]];

            // v[1][1] = center of pixel0, v[2][1] = center of pixel1 (never reflected)
            float lp0 = mask0[0] * v[0][0];
            float lp1 = mask1[0] * v[1][0];
            #pragma unroll
            for (int di = 0; di < 3; ++di)
                #pragma unroll
                for (int dj = 0; dj < 3; ++dj) {
                    if (di == 0 && dj == 0) continue;
                    lp0 = fmaf(mask0[di * 3 + dj], v[di][dj],     lp0);
                    lp1 = fmaf(mask1[di * 3 + dj], v[di + 1][dj], lp1);
                }

            const size_t co = (size_t)(ch * CHUNK + c) * HW;
            outb[co]       = 2.f * v[1][1] - lp0;
            outb[co + WWD] = 2.f * v[2][1] - lp1;
        }
    }
}

extern "C" void kernel_launch(void* const* d_in, const int* in_sizes, int n_in,
                              void* d_out, int out_size)
{
    const float* x  = (const float*)d_in[0];
    const float* Wt = (const float*)d_in[1];
    const float* bs = (const float*)d_in[2];
    float* out = (float*)d_out;

    const int B = in_sizes[0] / (CCH * HW);

    cudaFuncSetAttribute(ahpf_fused_kernel,
                         cudaFuncAttributeMaxDynamicSharedMemorySize, SMEM_BYTES);

    dim3 grid(WWD / TILE_W, HH / TILE_H, B);
    ahpf_fused_kernel<<<grid, 256, SMEM_BYTES>>>(x, Wt, bs, out);
}